// round 14
// baseline (speedup 1.0000x reference)
#include <cuda_runtime.h>
#include <cuda_fp16.h>
#include <math.h>
#include <stdint.h>

#define S_LEN   2048
#define DMODEL  2048
#define NHEADS  16
#define DK      128
#define NBATCH  4

// ---------------- static device scratch (fp16) ------------------------------
__device__ __half g_x16[3][(size_t)NBATCH * S_LEN * DMODEL];   // q,k,v inputs
__device__ __half g_w16[4][(size_t)DMODEL * DMODEL];           // wq,wk,wv,wo
__device__ __half g_q16[(size_t)NBATCH * S_LEN * DMODEL];
__device__ __half g_k16[(size_t)NBATCH * S_LEN * DMODEL];
__device__ __half g_v16[(size_t)NBATCH * S_LEN * DMODEL];
__device__ __half g_at16[(size_t)NBATCH * S_LEN * DMODEL];

// ======================= PTX helpers =======================================
__device__ __forceinline__ uint32_t smem_u32(const void* p) {
    uint32_t a;
    asm("{ .reg .u64 t; cvta.to.shared.u64 t, %1; cvt.u32.u64 %0, t; }" : "=r"(a) : "l"(p));
    return a;
}
#define CP_ASYNC16(dst, src) asm volatile("cp.async.cg.shared.global [%0], [%1], 16;" :: "r"(dst), "l"(src))
#define CP_COMMIT()          asm volatile("cp.async.commit_group;" ::: "memory")
#define CP_WAIT0()           asm volatile("cp.async.wait_group 0;" ::: "memory")
#define CP_WAIT1()           asm volatile("cp.async.wait_group 1;" ::: "memory")
#define CP_WAIT2()           asm volatile("cp.async.wait_group 2;" ::: "memory")

#define LDSM_X4(r0, r1, r2, r3, addr) \
    asm volatile("ldmatrix.sync.aligned.m8n8.x4.shared.b16 {%0,%1,%2,%3}, [%4];" \
        : "=r"(r0), "=r"(r1), "=r"(r2), "=r"(r3) : "r"(addr))
#define LDSM_X4_T(r0, r1, r2, r3, addr) \
    asm volatile("ldmatrix.sync.aligned.m8n8.x4.trans.shared.b16 {%0,%1,%2,%3}, [%4];" \
        : "=r"(r0), "=r"(r1), "=r"(r2), "=r"(r3) : "r"(addr))

#define MMA_F16(c, a, b0, b1) \
    asm volatile("mma.sync.aligned.m16n8k16.row.col.f32.f16.f16.f32 " \
        "{%0,%1,%2,%3},{%4,%5,%6,%7},{%8,%9},{%0,%1,%2,%3};" \
        : "+f"((c)[0]), "+f"((c)[1]), "+f"((c)[2]), "+f"((c)[3]) \
        : "r"((a)[0]), "r"((a)[1]), "r"((a)[2]), "r"((a)[3]), "r"(b0), "r"(b1))

__device__ __forceinline__ uint32_t packh(__half a, __half b) {
    __half2 t = __halves2half2(a, b);
    return *(uint32_t*)&t;
}

#define LDSB 80
#define ARR_BYTES (128 * LDSB)      // 10240

// ===========================================================================
// Pure fp16 1-pass NT GEMM body (unchanged)
// ===========================================================================
#define STG1 (2 * ARR_BYTES)        // 20480 (A, B)
#define SMEM1 (2 * STG1)            // 40960

__device__ __forceinline__ void gemm1_body(
    const __half* __restrict__ A, const __half* __restrict__ B,
    __half* __restrict__ C16, float* __restrict__ Cf)
{
    extern __shared__ char smem[];
    const uint32_t sb = smem_u32(smem);
    const int tid  = threadIdx.x;
    const int lane = tid & 31, wid = tid >> 5;
    const int wm   = wid & 3, wn = wid >> 2;
    const int row0 = blockIdx.y * 128;
    const int col0 = blockIdx.x * 128;

    const int nchunk = DMODEL >> 5;   // 64

    auto issue_stage = [&](int kt, int s) {
        const int k0 = kt << 5;
        const uint32_t sbase = sb + s * STG1;
#pragma unroll
        for (int i = 0; i < 2; i++) {
            const int c = tid + i * 256;
            const int r = c >> 2, q = c & 3;
            CP_ASYNC16(sbase + r * LDSB + q * 16,
                       A + (size_t)(row0 + r) * DMODEL + k0 + q * 8);
            CP_ASYNC16(sbase + ARR_BYTES + r * LDSB + q * 16,
                       B + (size_t)(col0 + r) * DMODEL + k0 + q * 8);
        }
        CP_COMMIT();
    };

    float acc[2][8][4];
#pragma unroll
    for (int mt = 0; mt < 2; mt++)
#pragma unroll
        for (int nt = 0; nt < 8; nt++)
#pragma unroll
            for (int r = 0; r < 4; r++) acc[mt][nt][r] = 0.0f;

    const int arow  = wm * 32 + (lane & 15);
    const int acolb = ((lane >> 4) << 3) * 2;
    const int brow  = wn * 64 + (lane & 7) + ((lane >> 4) & 1) * 8;
    const int bcolb = (((lane >> 3) & 1) << 3) * 2;

    auto compute_stage = [&](int s) {
        const uint32_t sbase = sb + s * STG1;
        const uint32_t sA = sbase;
        const uint32_t sB = sbase + ARR_BYTES;
#pragma unroll
        for (int h = 0; h < 2; h++) {
            const int kb = h * 32;
            uint32_t a0[4], a1[4];
            {
                uint32_t ad = sA + arow * LDSB + acolb + kb;
                LDSM_X4(a0[0], a0[1], a0[2], a0[3], ad);
                LDSM_X4(a1[0], a1[1], a1[2], a1[3], ad + 16 * LDSB);
            }
#pragma unroll
            for (int np = 0; np < 4; np++) {
                uint32_t bq[4];
                const uint32_t bo = (brow + np * 16) * LDSB + bcolb + kb;
                LDSM_X4(bq[0], bq[1], bq[2], bq[3], sB + bo);
#pragma unroll
                for (int u = 0; u < 2; u++) {
                    MMA_F16(acc[0][np * 2 + u], a0, bq[2 * u], bq[2 * u + 1]);
                    MMA_F16(acc[1][np * 2 + u], a1, bq[2 * u], bq[2 * u + 1]);
                }
            }
        }
    };

    issue_stage(0, 0);
    issue_stage(1, 1);
    for (int t = 0; t < nchunk; t++) {
        if (t + 2 < nchunk) { CP_WAIT1(); } else { CP_WAIT0(); }
        __syncthreads();
        compute_stage(t & 1);
        __syncthreads();
        if (t + 2 < nchunk) issue_stage(t + 2, t & 1);
    }

#pragma unroll
    for (int mt = 0; mt < 2; mt++) {
#pragma unroll
        for (int nt = 0; nt < 8; nt++) {
            const int r  = row0 + wm * 32 + mt * 16 + (lane >> 2);
            const int cc = col0 + wn * 64 + nt * 8 + (lane & 3) * 2;
            if (Cf == nullptr) {
                *(__half2*)(C16 + (size_t)r * DMODEL + cc) =
                    __halves2half2(__float2half_rn(acc[mt][nt][0]), __float2half_rn(acc[mt][nt][1]));
                *(__half2*)(C16 + (size_t)(r + 8) * DMODEL + cc) =
                    __halves2half2(__float2half_rn(acc[mt][nt][2]), __float2half_rn(acc[mt][nt][3]));
            } else {
                float* p = Cf + (size_t)r * DMODEL + cc;
                *(float2*)p = make_float2(acc[mt][nt][0], acc[mt][nt][1]);
                *(float2*)(p + 8 * DMODEL) = make_float2(acc[mt][nt][2], acc[mt][nt][3]);
            }
        }
    }
}

__global__ __launch_bounds__(256, 2) void gemm_qkv3(
    const __half* __restrict__ xall, const __half* __restrict__ wall,
    __half* __restrict__ q16, __half* __restrict__ k16, __half* __restrict__ v16)
{
    const int z = blockIdx.z;
    const size_t NACT = (size_t)NBATCH * S_LEN * DMODEL;
    const size_t NW   = (size_t)DMODEL * DMODEL;
    __half* C = (z == 0) ? q16 : ((z == 1) ? k16 : v16);
    gemm1_body(xall + (size_t)z * NACT, wall + (size_t)z * NW, C, nullptr);
}

__global__ __launch_bounds__(256, 2) void gemm_wo(
    const __half* __restrict__ A16, const __half* __restrict__ B16,
    float* __restrict__ Cf)
{
    gemm1_body(A16, B16, nullptr, Cf);
}

// ===========================================================================
// fp32 -> fp16 rounding, z-batched over up to 4 tensors
// ===========================================================================
__global__ __launch_bounds__(256) void conv_h(
    const float* __restrict__ x0, const float* __restrict__ x1,
    const float* __restrict__ x2, const float* __restrict__ x3,
    __half* __restrict__ y0, __half* __restrict__ y1,
    __half* __restrict__ y2, __half* __restrict__ y3, int n4)
{
    const int z = blockIdx.y;
    const float* x = (z == 0) ? x0 : ((z == 1) ? x1 : ((z == 2) ? x2 : x3));
    __half* y = (z == 0) ? y0 : ((z == 1) ? y1 : ((z == 2) ? y2 : y3));
    int i = blockIdx.x * 256 + threadIdx.x;
    if (i >= n4) return;
    float4 v = ((const float4*)x)[i];
    ((__half2*)y)[2 * i + 0] = __halves2half2(__float2half_rn(v.x), __float2half_rn(v.y));
    ((__half2*)y)[2 * i + 1] = __halves2half2(__float2half_rn(v.z), __float2half_rn(v.w));
}

// ===========================================================================
// Fused flash attention, pure fp16.
// 128-thread CTA, 64 Q rows, 2 CTAs/SM. Q fragments hoisted to registers;
// accO rescale skipped when the running max is unchanged (warp-uniform).
// ===========================================================================
#define FA_LDSB    272
#define FA_QROWS   64
#define FA_QTILE   (FA_QROWS * FA_LDSB)          // 17408
#define FA_KVTILE  (64 * FA_LDSB)                // 17408
#define FA_KVSTG   (2 * FA_KVTILE)               // 34816 (K + V)
#define FA_SMEM    (FA_QTILE + 2 * FA_KVSTG)     // 87040

__global__ __launch_bounds__(128, 2) void fused_attn(
    const __half* __restrict__ Q16, const __half* __restrict__ K16,
    const __half* __restrict__ V16, __half* __restrict__ O16)
{
    extern __shared__ char smem[];
    const uint32_t sb = smem_u32(smem);
    const int tid  = threadIdx.x;
    const int lane = tid & 31, wid = tid >> 5;       // 4 warps x 16 rows
    const int qrow0 = blockIdx.x * FA_QROWS;
    const int z  = blockIdx.y;
    const int bb = z >> 4, hh = z & 15;
    const size_t base = (size_t)bb * S_LEN * DMODEL + (size_t)hh * DK;

    const __half* qsrc = Q16 + base;
    const __half* kvsrc[2] = {K16 + base, V16 + base};

    const uint32_t sQ = sb;
    const uint32_t sKV = sb + FA_QTILE;

    // Q prologue (own cp.async group)
#pragma unroll
    for (int i = 0; i < 8; i++) {
        const int c = tid + i * 128;
        const int r = c >> 4, q = c & 15;
        CP_ASYNC16(sQ + r * FA_LDSB + q * 16,
                   qsrc + (size_t)(qrow0 + r) * DMODEL + q * 8);
    }
    CP_COMMIT();

    auto issue_stage = [&](int j, int s) {
        const int s0 = j << 6;
        const uint32_t sbase = sKV + s * FA_KVSTG;
#pragma unroll
        for (int i = 0; i < 16; i++) {
            const int c = tid + i * 128;             // 0..2047
            const int t = c >> 10, rem = c & 1023;
            const int r = rem >> 4, q = rem & 15;
            CP_ASYNC16(sbase + t * FA_KVTILE + r * FA_LDSB + q * 16,
                       kvsrc[t] + (size_t)(s0 + r) * DMODEL + q * 8);
        }
        CP_COMMIT();
    };
    issue_stage(0, 0);
    issue_stage(1, 1);

    const int arow  = wid * 16 + (lane & 15);
    const int acolb = (lane >> 4) * 16;
    const int brow  = (lane & 7) + ((lane >> 4) & 1) * 8;
    const int bcolb = ((lane >> 3) & 1) * 16;
    const int btr   = (lane & 7) + ((lane >> 3) & 1) * 8;
    const int btc   = ((lane >> 4) & 1) * 8;

    // hoist Q fragments into registers (Q group done after wait_group 2)
    CP_WAIT2();
    __syncthreads();
    uint32_t qfrag[8][4];
#pragma unroll
    for (int kst = 0; kst < 8; kst++) {
        LDSM_X4(qfrag[kst][0], qfrag[kst][1], qfrag[kst][2], qfrag[kst][3],
                sQ + arow * FA_LDSB + acolb + kst * 32);
    }

    float accO[16][4];
#pragma unroll
    for (int nt = 0; nt < 16; nt++)
#pragma unroll
        for (int r = 0; r < 4; r++) accO[nt][r] = 0.0f;
    float mrow[2] = {-1e30f, -1e30f};
    float lrow[2] = {0.0f, 0.0f};
    const float csc = 0.08838834764831845f;

    const int NITER = S_LEN / 64;                    // 32
    for (int j = 0; j < NITER; j++) {
        if (j + 2 < NITER) { CP_WAIT1(); } else { CP_WAIT0(); }
        __syncthreads();
        const uint32_t st = sKV + (j & 1) * FA_KVSTG;
        const uint32_t sK = st;
        const uint32_t sV = st + FA_KVTILE;

        // ---- S = Q K^T -----------------------------------------------------
        float sacc[8][4];
#pragma unroll
        for (int nt = 0; nt < 8; nt++)
#pragma unroll
            for (int r = 0; r < 4; r++) sacc[nt][r] = 0.0f;

#pragma unroll
        for (int kst = 0; kst < 8; kst++) {
            const int kb = kst * 32;
#pragma unroll
            for (int np = 0; np < 4; np++) {
                const uint32_t bo = (uint32_t)(brow + np * 16) * FA_LDSB + bcolb + kb;
                uint32_t kq[4];
                LDSM_X4(kq[0], kq[1], kq[2], kq[3], sK + bo);
#pragma unroll
                for (int u = 0; u < 2; u++)
                    MMA_F16(sacc[np * 2 + u], qfrag[kst], kq[2 * u], kq[2 * u + 1]);
            }
        }

        // ---- online softmax (row stats) ------------------------------------
        float mnew[2] = {mrow[0], mrow[1]};
#pragma unroll
        for (int nt = 0; nt < 8; nt++) {
            mnew[0] = fmaxf(mnew[0], fmaxf(sacc[nt][0], sacc[nt][1]));
            mnew[1] = fmaxf(mnew[1], fmaxf(sacc[nt][2], sacc[nt][3]));
        }
#pragma unroll
        for (int o = 1; o <= 2; o <<= 1) {
            mnew[0] = fmaxf(mnew[0], __shfl_xor_sync(0xffffffffu, mnew[0], o));
            mnew[1] = fmaxf(mnew[1], __shfl_xor_sync(0xffffffffu, mnew[1], o));
        }
        // rescale-skip: if no lane's max changed, accO/lrow scale is exactly 1
        const bool changed = (mnew[0] != mrow[0]) | (mnew[1] != mrow[1]);
        if (__any_sync(0xffffffffu, changed)) {
            const float sc0 = __expf((mrow[0] - mnew[0]) * csc);
            const float sc1 = __expf((mrow[1] - mnew[1]) * csc);
            mrow[0] = mnew[0]; mrow[1] = mnew[1];
            lrow[0] *= sc0; lrow[1] *= sc1;
#pragma unroll
            for (int nt = 0; nt < 16; nt++) {
                accO[nt][0] *= sc0; accO[nt][1] *= sc0;
                accO[nt][2] *= sc1; accO[nt][3] *= sc1;
            }
        }

        // ---- P exp/pack interleaved with PV MMAs ---------------------------
        float ls0 = 0.0f, ls1 = 0.0f;
#pragma unroll
        for (int t2 = 0; t2 < 4; t2++) {
            uint32_t ph[4];
#pragma unroll
            for (int half = 0; half < 2; half++) {
                float* s = sacc[2 * t2 + half];
                float p0 = __expf((s[0] - mnew[0]) * csc);
                float p1 = __expf((s[1] - mnew[0]) * csc);
                float p2 = __expf((s[2] - mnew[1]) * csc);
                float p3 = __expf((s[3] - mnew[1]) * csc);
                ls0 += p0 + p1; ls1 += p2 + p3;
                ph[2 * half + 0] = packh(__float2half_rn(p0), __float2half_rn(p1));
                ph[2 * half + 1] = packh(__float2half_rn(p2), __float2half_rn(p3));
            }
#pragma unroll
            for (int np = 0; np < 8; np++) {
                const uint32_t bo = (uint32_t)(t2 * 16 + btr) * FA_LDSB + (np * 16 + btc) * 2;
                uint32_t vq[4];
                LDSM_X4_T(vq[0], vq[1], vq[2], vq[3], sV + bo);
#pragma unroll
                for (int u = 0; u < 2; u++)
                    MMA_F16(accO[np * 2 + u], ph, vq[2 * u], vq[2 * u + 1]);
            }
        }
        lrow[0] += ls0; lrow[1] += ls1;

        __syncthreads();
        if (j + 2 < NITER) issue_stage(j + 2, j & 1);
    }

    // ---- epilogue ----------------------------------------------------------
#pragma unroll
    for (int o = 1; o <= 2; o <<= 1) {
        lrow[0] += __shfl_xor_sync(0xffffffffu, lrow[0], o);
        lrow[1] += __shfl_xor_sync(0xffffffffu, lrow[1], o);
    }
    const float inv0 = 1.0f / lrow[0];
    const float inv1 = 1.0f / lrow[1];
    const int r0 = qrow0 + wid * 16 + (lane >> 2);
#pragma unroll
    for (int nt = 0; nt < 16; nt++) {
        const int cc = nt * 8 + (lane & 3) * 2;
        *(__half2*)(O16 + base + (size_t)r0 * DMODEL + cc) =
            __halves2half2(__float2half_rn(accO[nt][0] * inv0),
                           __float2half_rn(accO[nt][1] * inv0));
        *(__half2*)(O16 + base + (size_t)(r0 + 8) * DMODEL + cc) =
            __halves2half2(__float2half_rn(accO[nt][2] * inv1),
                           __float2half_rn(accO[nt][3] * inv1));
    }
}

// ---------------------------------------------------------------------------
extern "C" void kernel_launch(void* const* d_in, const int* in_sizes, int n_in,
                              void* d_out, int out_size)
{
    const float* q   = (const float*)d_in[0];
    const float* k   = (const float*)d_in[1];
    const float* v   = (const float*)d_in[2];
    const float* w_q = (const float*)d_in[3];
    const float* w_k = (const float*)d_in[4];
    const float* w_v = (const float*)d_in[5];
    const float* w_o = (const float*)d_in[6];
    float* out = (float*)d_out;

    __half *x16, *w16, *q16, *k16, *v16, *at16;
    cudaGetSymbolAddress((void**)&x16, g_x16);
    cudaGetSymbolAddress((void**)&w16, g_w16);
    cudaGetSymbolAddress((void**)&q16, g_q16);
    cudaGetSymbolAddress((void**)&k16, g_k16);
    cudaGetSymbolAddress((void**)&v16, g_v16);
    cudaGetSymbolAddress((void**)&at16, g_at16);

    cudaFuncSetAttribute(gemm_qkv3, cudaFuncAttributeMaxDynamicSharedMemorySize, SMEM1);
    cudaFuncSetAttribute(gemm_wo, cudaFuncAttributeMaxDynamicSharedMemorySize, SMEM1);
    cudaFuncSetAttribute(fused_attn, cudaFuncAttributeMaxDynamicSharedMemorySize, FA_SMEM);

    const int M_rows = NBATCH * S_LEN;
    const size_t NACT = (size_t)M_rows * DMODEL;
    const size_t NW   = (size_t)DMODEL * DMODEL;
    const int nact4 = (int)(NACT / 4);
    const int nw4   = (int)(NW / 4);
    dim3 blk(256);

    // 1) Round inputs and weights to fp16
    {
        dim3 ga((nact4 + 255) / 256, 3);
        conv_h<<<ga, blk>>>(q, k, v, nullptr,
                            x16, x16 + NACT, x16 + 2 * NACT, nullptr, nact4);
        dim3 gw((nw4 + 255) / 256, 4);
        conv_h<<<gw, blk>>>(w_q, w_k, w_v, w_o,
                            w16, w16 + NW, w16 + 2 * NW, w16 + 3 * NW, nw4);
    }

    // 2) QKV projections (pure fp16 1-pass, one launch)
    {
        dim3 grid(DMODEL / 128, M_rows / 128, 3);
        gemm_qkv3<<<grid, blk, SMEM1>>>(x16, w16, q16, k16, v16);
    }

    // 3) Fused attention: 64 Q-rows per 128-thread CTA, 2 CTAs/SM
    {
        dim3 grid(S_LEN / FA_QROWS, NBATCH * NHEADS);
        fused_attn<<<grid, 128, FA_SMEM>>>(q16, k16, v16, at16);
    }

    // 4) Output projection (pure fp16 1-pass) -> fp32 d_out
    {
        dim3 grid(DMODEL / 128, M_rows / 128);
        gemm_wo<<<grid, blk, SMEM1>>>(at16, w16 + 3 * NW, out);
    }
}

// round 15
// speedup vs baseline: 1.4983x; 1.4983x over previous
#include <cuda_runtime.h>
#include <cuda_fp16.h>
#include <math.h>
#include <stdint.h>

#define S_LEN   2048
#define DMODEL  2048
#define NHEADS  16
#define DK      128
#define NBATCH  4

// ---------------- static device scratch (fp16) ------------------------------
__device__ __half g_x16[3][(size_t)NBATCH * S_LEN * DMODEL];   // q,k,v inputs
__device__ __half g_w16[4][(size_t)DMODEL * DMODEL];           // wq,wk,wv,wo
__device__ __half g_q16[(size_t)NBATCH * S_LEN * DMODEL];
__device__ __half g_k16[(size_t)NBATCH * S_LEN * DMODEL];
__device__ __half g_v16[(size_t)NBATCH * S_LEN * DMODEL];
__device__ __half g_at16[(size_t)NBATCH * S_LEN * DMODEL];

// ======================= PTX helpers =======================================
__device__ __forceinline__ uint32_t smem_u32(const void* p) {
    uint32_t a;
    asm("{ .reg .u64 t; cvta.to.shared.u64 t, %1; cvt.u32.u64 %0, t; }" : "=r"(a) : "l"(p));
    return a;
}
#define CP_ASYNC16(dst, src) asm volatile("cp.async.cg.shared.global [%0], [%1], 16;" :: "r"(dst), "l"(src))
#define CP_COMMIT()          asm volatile("cp.async.commit_group;" ::: "memory")
#define CP_WAIT0()           asm volatile("cp.async.wait_group 0;" ::: "memory")
#define CP_WAIT1()           asm volatile("cp.async.wait_group 1;" ::: "memory")

#define LDSM_X4(r0, r1, r2, r3, addr) \
    asm volatile("ldmatrix.sync.aligned.m8n8.x4.shared.b16 {%0,%1,%2,%3}, [%4];" \
        : "=r"(r0), "=r"(r1), "=r"(r2), "=r"(r3) : "r"(addr))
#define LDSM_X4_T(r0, r1, r2, r3, addr) \
    asm volatile("ldmatrix.sync.aligned.m8n8.x4.trans.shared.b16 {%0,%1,%2,%3}, [%4];" \
        : "=r"(r0), "=r"(r1), "=r"(r2), "=r"(r3) : "r"(addr))

#define MMA_F16(c, a, b0, b1) \
    asm volatile("mma.sync.aligned.m16n8k16.row.col.f32.f16.f16.f32 " \
        "{%0,%1,%2,%3},{%4,%5,%6,%7},{%8,%9},{%0,%1,%2,%3};" \
        : "+f"((c)[0]), "+f"((c)[1]), "+f"((c)[2]), "+f"((c)[3]) \
        : "r"((a)[0]), "r"((a)[1]), "r"((a)[2]), "r"((a)[3]), "r"(b0), "r"(b1))

__device__ __forceinline__ uint32_t packh(__half a, __half b) {
    __half2 t = __halves2half2(a, b);
    return *(uint32_t*)&t;
}

#define LDSB 80
#define ARR_BYTES (128 * LDSB)      // 10240

// ===========================================================================
// Pure fp16 1-pass NT GEMM body (unchanged from Round 12/13)
// ===========================================================================
#define STG1 (2 * ARR_BYTES)        // 20480 (A, B)
#define SMEM1 (2 * STG1)            // 40960

__device__ __forceinline__ void gemm1_body(
    const __half* __restrict__ A, const __half* __restrict__ B,
    __half* __restrict__ C16, float* __restrict__ Cf)
{
    extern __shared__ char smem[];
    const uint32_t sb = smem_u32(smem);
    const int tid  = threadIdx.x;
    const int lane = tid & 31, wid = tid >> 5;
    const int wm   = wid & 3, wn = wid >> 2;
    const int row0 = blockIdx.y * 128;
    const int col0 = blockIdx.x * 128;

    const int nchunk = DMODEL >> 5;   // 64

    auto issue_stage = [&](int kt, int s) {
        const int k0 = kt << 5;
        const uint32_t sbase = sb + s * STG1;
#pragma unroll
        for (int i = 0; i < 2; i++) {
            const int c = tid + i * 256;
            const int r = c >> 2, q = c & 3;
            CP_ASYNC16(sbase + r * LDSB + q * 16,
                       A + (size_t)(row0 + r) * DMODEL + k0 + q * 8);
            CP_ASYNC16(sbase + ARR_BYTES + r * LDSB + q * 16,
                       B + (size_t)(col0 + r) * DMODEL + k0 + q * 8);
        }
        CP_COMMIT();
    };

    float acc[2][8][4];
#pragma unroll
    for (int mt = 0; mt < 2; mt++)
#pragma unroll
        for (int nt = 0; nt < 8; nt++)
#pragma unroll
            for (int r = 0; r < 4; r++) acc[mt][nt][r] = 0.0f;

    const int arow  = wm * 32 + (lane & 15);
    const int acolb = ((lane >> 4) << 3) * 2;
    const int brow  = wn * 64 + (lane & 7) + ((lane >> 4) & 1) * 8;
    const int bcolb = (((lane >> 3) & 1) << 3) * 2;

    auto compute_stage = [&](int s) {
        const uint32_t sbase = sb + s * STG1;
        const uint32_t sA = sbase;
        const uint32_t sB = sbase + ARR_BYTES;
#pragma unroll
        for (int h = 0; h < 2; h++) {
            const int kb = h * 32;
            uint32_t a0[4], a1[4];
            {
                uint32_t ad = sA + arow * LDSB + acolb + kb;
                LDSM_X4(a0[0], a0[1], a0[2], a0[3], ad);
                LDSM_X4(a1[0], a1[1], a1[2], a1[3], ad + 16 * LDSB);
            }
#pragma unroll
            for (int np = 0; np < 4; np++) {
                uint32_t bq[4];
                const uint32_t bo = (brow + np * 16) * LDSB + bcolb + kb;
                LDSM_X4(bq[0], bq[1], bq[2], bq[3], sB + bo);
#pragma unroll
                for (int u = 0; u < 2; u++) {
                    MMA_F16(acc[0][np * 2 + u], a0, bq[2 * u], bq[2 * u + 1]);
                    MMA_F16(acc[1][np * 2 + u], a1, bq[2 * u], bq[2 * u + 1]);
                }
            }
        }
    };

    issue_stage(0, 0);
    issue_stage(1, 1);
    for (int t = 0; t < nchunk; t++) {
        if (t + 2 < nchunk) { CP_WAIT1(); } else { CP_WAIT0(); }
        __syncthreads();
        compute_stage(t & 1);
        __syncthreads();
        if (t + 2 < nchunk) issue_stage(t + 2, t & 1);
    }

#pragma unroll
    for (int mt = 0; mt < 2; mt++) {
#pragma unroll
        for (int nt = 0; nt < 8; nt++) {
            const int r  = row0 + wm * 32 + mt * 16 + (lane >> 2);
            const int cc = col0 + wn * 64 + nt * 8 + (lane & 3) * 2;
            if (Cf == nullptr) {
                *(__half2*)(C16 + (size_t)r * DMODEL + cc) =
                    __halves2half2(__float2half_rn(acc[mt][nt][0]), __float2half_rn(acc[mt][nt][1]));
                *(__half2*)(C16 + (size_t)(r + 8) * DMODEL + cc) =
                    __halves2half2(__float2half_rn(acc[mt][nt][2]), __float2half_rn(acc[mt][nt][3]));
            } else {
                float* p = Cf + (size_t)r * DMODEL + cc;
                *(float2*)p = make_float2(acc[mt][nt][0], acc[mt][nt][1]);
                *(float2*)(p + 8 * DMODEL) = make_float2(acc[mt][nt][2], acc[mt][nt][3]);
            }
        }
    }
}

__global__ __launch_bounds__(256, 2) void gemm_qkv3(
    const __half* __restrict__ xall, const __half* __restrict__ wall,
    __half* __restrict__ q16, __half* __restrict__ k16, __half* __restrict__ v16)
{
    const int z = blockIdx.z;
    const size_t NACT = (size_t)NBATCH * S_LEN * DMODEL;
    const size_t NW   = (size_t)DMODEL * DMODEL;
    __half* C = (z == 0) ? q16 : ((z == 1) ? k16 : v16);
    gemm1_body(xall + (size_t)z * NACT, wall + (size_t)z * NW, C, nullptr);
}

__global__ __launch_bounds__(256, 2) void gemm_wo(
    const __half* __restrict__ A16, const __half* __restrict__ B16,
    float* __restrict__ Cf)
{
    gemm1_body(A16, B16, nullptr, Cf);
}

// ===========================================================================
// fp32 -> fp16 rounding, z-batched over up to 4 tensors
// ===========================================================================
__global__ __launch_bounds__(256) void conv_h(
    const float* __restrict__ x0, const float* __restrict__ x1,
    const float* __restrict__ x2, const float* __restrict__ x3,
    __half* __restrict__ y0, __half* __restrict__ y1,
    __half* __restrict__ y2, __half* __restrict__ y3, int n4)
{
    const int z = blockIdx.y;
    const float* x = (z == 0) ? x0 : ((z == 1) ? x1 : ((z == 2) ? x2 : x3));
    __half* y = (z == 0) ? y0 : ((z == 1) ? y1 : ((z == 2) ? y2 : y3));
    int i = blockIdx.x * 256 + threadIdx.x;
    if (i >= n4) return;
    float4 v = ((const float4*)x)[i];
    ((__half2*)y)[2 * i + 0] = __halves2half2(__float2half_rn(v.x), __float2half_rn(v.y));
    ((__half2*)y)[2 * i + 1] = __halves2half2(__float2half_rn(v.z), __float2half_rn(v.w));
}

// ===========================================================================
// Fused flash attention, pure fp16 — Round-13 structure (Q re-LDSM'd
// per iteration, Q in stage-0 commit group) + exact rescale-skip.
// 128-thread CTA, 64 Q rows, 2 CTAs/SM.
// ===========================================================================
#define FA_LDSB    272
#define FA_QROWS   64
#define FA_QTILE   (FA_QROWS * FA_LDSB)          // 17408
#define FA_KVTILE  (64 * FA_LDSB)                // 17408
#define FA_KVSTG   (2 * FA_KVTILE)               // 34816 (K + V)
#define FA_SMEM    (FA_QTILE + 2 * FA_KVSTG)     // 87040

__global__ __launch_bounds__(128, 2) void fused_attn(
    const __half* __restrict__ Q16, const __half* __restrict__ K16,
    const __half* __restrict__ V16, __half* __restrict__ O16)
{
    extern __shared__ char smem[];
    const uint32_t sb = smem_u32(smem);
    const int tid  = threadIdx.x;
    const int lane = tid & 31, wid = tid >> 5;       // 4 warps x 16 rows
    const int qrow0 = blockIdx.x * FA_QROWS;
    const int z  = blockIdx.y;
    const int bb = z >> 4, hh = z & 15;
    const size_t base = (size_t)bb * S_LEN * DMODEL + (size_t)hh * DK;

    const __half* qsrc = Q16 + base;
    const __half* kvsrc[2] = {K16 + base, V16 + base};

    const uint32_t sQ = sb;
    const uint32_t sKV = sb + FA_QTILE;

    // Q prologue: committed together with stage 0 (Round-13 grouping)
#pragma unroll
    for (int i = 0; i < 8; i++) {
        const int c = tid + i * 128;
        const int r = c >> 4, q = c & 15;
        CP_ASYNC16(sQ + r * FA_LDSB + q * 16,
                   qsrc + (size_t)(qrow0 + r) * DMODEL + q * 8);
    }
    auto issue_stage = [&](int j, int s) {
        const int s0 = j << 6;
        const uint32_t sbase = sKV + s * FA_KVSTG;
#pragma unroll
        for (int i = 0; i < 16; i++) {
            const int c = tid + i * 128;             // 0..2047
            const int t = c >> 10, rem = c & 1023;
            const int r = rem >> 4, q = rem & 15;
            CP_ASYNC16(sbase + t * FA_KVTILE + r * FA_LDSB + q * 16,
                       kvsrc[t] + (size_t)(s0 + r) * DMODEL + q * 8);
        }
        CP_COMMIT();
    };
    issue_stage(0, 0);
    issue_stage(1, 1);

    float accO[16][4];
#pragma unroll
    for (int nt = 0; nt < 16; nt++)
#pragma unroll
        for (int r = 0; r < 4; r++) accO[nt][r] = 0.0f;
    float mrow[2] = {-1e30f, -1e30f};
    float lrow[2] = {0.0f, 0.0f};
    const float csc = 0.08838834764831845f;

    const int arow  = wid * 16 + (lane & 15);
    const int acolb = (lane >> 4) * 16;
    const int brow  = (lane & 7) + ((lane >> 4) & 1) * 8;
    const int bcolb = ((lane >> 3) & 1) * 16;
    const int btr   = (lane & 7) + ((lane >> 3) & 1) * 8;
    const int btc   = ((lane >> 4) & 1) * 8;

    const int NITER = S_LEN / 64;                    // 32
    for (int j = 0; j < NITER; j++) {
        if (j + 2 < NITER) { CP_WAIT1(); } else { CP_WAIT0(); }
        __syncthreads();
        const uint32_t st = sKV + (j & 1) * FA_KVSTG;
        const uint32_t sK = st;
        const uint32_t sV = st + FA_KVTILE;

        // ---- S = Q K^T -----------------------------------------------------
        float sacc[8][4];
#pragma unroll
        for (int nt = 0; nt < 8; nt++)
#pragma unroll
            for (int r = 0; r < 4; r++) sacc[nt][r] = 0.0f;

#pragma unroll
        for (int kst = 0; kst < 8; kst++) {
            const int kb = kst * 32;
            uint32_t qh[4];
            LDSM_X4(qh[0], qh[1], qh[2], qh[3], sQ + arow * FA_LDSB + acolb + kb);
#pragma unroll
            for (int np = 0; np < 4; np++) {
                const uint32_t bo = (uint32_t)(brow + np * 16) * FA_LDSB + bcolb + kb;
                uint32_t kq[4];
                LDSM_X4(kq[0], kq[1], kq[2], kq[3], sK + bo);
#pragma unroll
                for (int u = 0; u < 2; u++)
                    MMA_F16(sacc[np * 2 + u], qh, kq[2 * u], kq[2 * u + 1]);
            }
        }

        // ---- online softmax (row stats) ------------------------------------
        float mnew[2] = {mrow[0], mrow[1]};
#pragma unroll
        for (int nt = 0; nt < 8; nt++) {
            mnew[0] = fmaxf(mnew[0], fmaxf(sacc[nt][0], sacc[nt][1]));
            mnew[1] = fmaxf(mnew[1], fmaxf(sacc[nt][2], sacc[nt][3]));
        }
#pragma unroll
        for (int o = 1; o <= 2; o <<= 1) {
            mnew[0] = fmaxf(mnew[0], __shfl_xor_sync(0xffffffffu, mnew[0], o));
            mnew[1] = fmaxf(mnew[1], __shfl_xor_sync(0xffffffffu, mnew[1], o));
        }
        // exact rescale-skip: if no lane's max changed, the scale is exactly 1
        const bool changed = (mnew[0] != mrow[0]) | (mnew[1] != mrow[1]);
        if (__any_sync(0xffffffffu, changed)) {
            const float sc0 = __expf((mrow[0] - mnew[0]) * csc);
            const float sc1 = __expf((mrow[1] - mnew[1]) * csc);
            mrow[0] = mnew[0]; mrow[1] = mnew[1];
            lrow[0] *= sc0; lrow[1] *= sc1;
#pragma unroll
            for (int nt = 0; nt < 16; nt++) {
                accO[nt][0] *= sc0; accO[nt][1] *= sc0;
                accO[nt][2] *= sc1; accO[nt][3] *= sc1;
            }
        }

        // ---- P exp/pack interleaved with PV MMAs ---------------------------
        float ls0 = 0.0f, ls1 = 0.0f;
#pragma unroll
        for (int t2 = 0; t2 < 4; t2++) {
            uint32_t ph[4];
#pragma unroll
            for (int half = 0; half < 2; half++) {
                float* s = sacc[2 * t2 + half];
                float p0 = __expf((s[0] - mnew[0]) * csc);
                float p1 = __expf((s[1] - mnew[0]) * csc);
                float p2 = __expf((s[2] - mnew[1]) * csc);
                float p3 = __expf((s[3] - mnew[1]) * csc);
                ls0 += p0 + p1; ls1 += p2 + p3;
                ph[2 * half + 0] = packh(__float2half_rn(p0), __float2half_rn(p1));
                ph[2 * half + 1] = packh(__float2half_rn(p2), __float2half_rn(p3));
            }
#pragma unroll
            for (int np = 0; np < 8; np++) {
                const uint32_t bo = (uint32_t)(t2 * 16 + btr) * FA_LDSB + (np * 16 + btc) * 2;
                uint32_t vq[4];
                LDSM_X4_T(vq[0], vq[1], vq[2], vq[3], sV + bo);
#pragma unroll
                for (int u = 0; u < 2; u++)
                    MMA_F16(accO[np * 2 + u], ph, vq[2 * u], vq[2 * u + 1]);
            }
        }
        lrow[0] += ls0; lrow[1] += ls1;

        __syncthreads();
        if (j + 2 < NITER) issue_stage(j + 2, j & 1);
    }

    // ---- epilogue ----------------------------------------------------------
#pragma unroll
    for (int o = 1; o <= 2; o <<= 1) {
        lrow[0] += __shfl_xor_sync(0xffffffffu, lrow[0], o);
        lrow[1] += __shfl_xor_sync(0xffffffffu, lrow[1], o);
    }
    const float inv0 = 1.0f / lrow[0];
    const float inv1 = 1.0f / lrow[1];
    const int r0 = qrow0 + wid * 16 + (lane >> 2);
#pragma unroll
    for (int nt = 0; nt < 16; nt++) {
        const int cc = nt * 8 + (lane & 3) * 2;
        *(__half2*)(O16 + base + (size_t)r0 * DMODEL + cc) =
            __halves2half2(__float2half_rn(accO[nt][0] * inv0),
                           __float2half_rn(accO[nt][1] * inv0));
        *(__half2*)(O16 + base + (size_t)(r0 + 8) * DMODEL + cc) =
            __halves2half2(__float2half_rn(accO[nt][2] * inv1),
                           __float2half_rn(accO[nt][3] * inv1));
    }
}

// ---------------------------------------------------------------------------
extern "C" void kernel_launch(void* const* d_in, const int* in_sizes, int n_in,
                              void* d_out, int out_size)
{
    const float* q   = (const float*)d_in[0];
    const float* k   = (const float*)d_in[1];
    const float* v   = (const float*)d_in[2];
    const float* w_q = (const float*)d_in[3];
    const float* w_k = (const float*)d_in[4];
    const float* w_v = (const float*)d_in[5];
    const float* w_o = (const float*)d_in[6];
    float* out = (float*)d_out;

    __half *x16, *w16, *q16, *k16, *v16, *at16;
    cudaGetSymbolAddress((void**)&x16, g_x16);
    cudaGetSymbolAddress((void**)&w16, g_w16);
    cudaGetSymbolAddress((void**)&q16, g_q16);
    cudaGetSymbolAddress((void**)&k16, g_k16);
    cudaGetSymbolAddress((void**)&v16, g_v16);
    cudaGetSymbolAddress((void**)&at16, g_at16);

    cudaFuncSetAttribute(gemm_qkv3, cudaFuncAttributeMaxDynamicSharedMemorySize, SMEM1);
    cudaFuncSetAttribute(gemm_wo, cudaFuncAttributeMaxDynamicSharedMemorySize, SMEM1);
    cudaFuncSetAttribute(fused_attn, cudaFuncAttributeMaxDynamicSharedMemorySize, FA_SMEM);

    const int M_rows = NBATCH * S_LEN;
    const size_t NACT = (size_t)M_rows * DMODEL;
    const size_t NW   = (size_t)DMODEL * DMODEL;
    const int nact4 = (int)(NACT / 4);
    const int nw4   = (int)(NW / 4);
    dim3 blk(256);

    // 1) Round inputs and weights to fp16
    {
        dim3 ga((nact4 + 255) / 256, 3);
        conv_h<<<ga, blk>>>(q, k, v, nullptr,
                            x16, x16 + NACT, x16 + 2 * NACT, nullptr, nact4);
        dim3 gw((nw4 + 255) / 256, 4);
        conv_h<<<gw, blk>>>(w_q, w_k, w_v, w_o,
                            w16, w16 + NW, w16 + 2 * NW, w16 + 3 * NW, nw4);
    }

    // 2) QKV projections (pure fp16 1-pass, one launch)
    {
        dim3 grid(DMODEL / 128, M_rows / 128, 3);
        gemm_qkv3<<<grid, blk, SMEM1>>>(x16, w16, q16, k16, v16);
    }

    // 3) Fused attention: 64 Q-rows per 128-thread CTA, 2 CTAs/SM
    {
        dim3 grid(S_LEN / FA_QROWS, NBATCH * NHEADS);
        fused_attn<<<grid, 128, FA_SMEM>>>(q16, k16, v16, at16);
    }

    // 4) Output projection (pure fp16 1-pass) -> fp32 d_out
    {
        dim3 grid(DMODEL / 128, M_rows / 128);
        gemm_wo<<<grid, blk, SMEM1>>>(at16, w16 + 3 * NW, out);
    }
}